// round 10
// baseline (speedup 1.0000x reference)
#include <cuda_runtime.h>
#include <math.h>

#ifndef M_PI
#define M_PI 3.14159265358979323846
#endif

#define MROWS 4096
#define ROWSTRIDE 74
#define GRP 128
#define NGRP 32
#define NTILES 528          // 32*33/2
#define NROWBLK 512
#define TABN 2048
#define FULLMASK 0xffffffffu

__device__ float2 g_zs[MROWS];
__device__ float2 g_tab[TABN];          // phi LUT over t = rsqrt(1+s)
__device__ double g_pairp[NTILES];
__device__ double g_rowp[NROWBLK][4];   // rec, ce, b, den
__device__ unsigned g_done;

// ---- small branch: poly in s^2, coeffs folded with (1/56.25)^k ----
#define P56 56.25
#define BC0 ((float)(3.5156229 / P56))
#define BC1 ((float)(3.0899424 / (P56 * P56)))
#define BC2 ((float)(1.2067492 / (P56 * P56 * P56)))
#define BC3 ((float)(0.2659732 / (P56 * P56 * P56 * P56)))
#define BC4 ((float)(0.0360768 / (P56 * P56 * P56 * P56 * P56)))
#define BC5 ((float)(0.0045813 / (P56 * P56 * P56 * P56 * P56 * P56)))
// ---- large branch: coeffs folded with sqrt(2)*7.5^k, poly in 1/s ----
#define SQ2 1.4142135623730951
#define QD0 ((float)(0.39894228 * SQ2))
#define QD1 ((float)(0.01328592 * SQ2 * 7.5))
#define QD2 ((float)(0.00225319 * SQ2 * 56.25))
#define QD3 ((float)(-0.00157565 * SQ2 * 421.875))
#define QD4 ((float)(0.0091628 * SQ2 * 3164.0625))
#define QD5 ((float)(-0.02057706 * SQ2 * 23730.46875))
#define QD6 ((float)(0.02635537 * SQ2 * 177978.515625))
#define QD7 ((float)(-0.01647633 * SQ2 * 1334838.8671875))
#define QD8 ((float)(0.00392377 * SQ2 * 10011291.50390625))

__device__ __forceinline__ float rsqa(float x) {
    float r; asm("rsqrt.approx.f32 %0,%1;" : "=f"(r) : "f"(x)); return r;
}

// exact reference phi (rows / finalize / table build)
__device__ __forceinline__ float phi_sel(float s, float K1) {
    float s2 = s * s;
    float p = fmaf(s2, BC5, BC4);
    p = fmaf(s2, p, BC3);
    p = fmaf(s2, p, BC2);
    p = fmaf(s2, p, BC1);
    p = fmaf(s2, p, BC0);
    p = fmaf(s2, p, 1.0f);
    float e  = __expf(-0.5f * s);
    float sv = fmaf(p, e, K1);
    float r  = rsqrtf(s);
    float iv = r * r;
    float q = fmaf(iv, QD8, QD7);
    q = fmaf(iv, q, QD6);
    q = fmaf(iv, q, QD5);
    q = fmaf(iv, q, QD4);
    q = fmaf(iv, q, QD3);
    q = fmaf(iv, q, QD2);
    q = fmaf(iv, q, QD1);
    q = fmaf(iv, q, QD0);
    float bv = r * q;
    return (s <= 7.5f) ? sv : bv;
}

__device__ __forceinline__ float phi_of_t(float t, float K1) {
    if (t <= 0.f) return 0.f;
    double td = (double)t;
    double sd = 1.0 / (td * td) - 1.0;
    if (sd < 0.0) sd = 0.0;
    return phi_sel((float)sd, K1);
}

__device__ __forceinline__ float ftanh(float x) {
    float e = __expf(2.f * x);
    return 1.f - __fdividef(2.f, e + 1.f);
}
__device__ __forceinline__ float wsum(float v) {
    #pragma unroll
    for (int o = 16; o; o >>= 1) v += __shfl_xor_sync(FULLMASK, v, o);
    return v;
}
__device__ __forceinline__ double wsumd(double v) {
    #pragma unroll
    for (int o = 16; o; o >>= 1) v += __shfl_xor_sync(FULLMASK, v, o);
    return v;
}
__device__ __forceinline__ float wmax(float v) {
    #pragma unroll
    for (int o = 16; o; o >>= 1) v = fmaxf(v, __shfl_xor_sync(FULLMASK, v, o));
    return v;
}

// ---------------- rows kernel: 512 blocks, 1 row/warp; block 0 builds LUT ----
__global__ void __launch_bounds__(256) k_rows(
    const float* __restrict__ bd,
    const float* __restrict__ We1, const float* __restrict__ be1,
    const float* __restrict__ We2, const float* __restrict__ be2,
    const float* __restrict__ We3, const float* __restrict__ be3,
    const float* __restrict__ Wd1, const float* __restrict__ bd1,
    const float* __restrict__ Wd2, const float* __restrict__ bd2,
    const float* __restrict__ Wd3, const float* __restrict__ bd3,
    const float* __restrict__ means, const float* __restrict__ vars,
    const float* __restrict__ probs,
    float K1, float rsc, float gam)
{
    __shared__ float sWe1[2048], sWe2[512], sWe3[32], sWd1[32], sWd2[512], sWd3[2048];
    __shared__ float sBe1[32], sBe2[16], sBe3[2], sBd1[16], sBd2[32], sBd3[64];
    __shared__ float sClsC[10], sInv2v[10], sBcoef[10], sBinv[10], sMu[20];
    __shared__ float stau[8][64], sh1[8][32], sh2[8][16], sd1[8][16], sd2[8][32];
    __shared__ double sRed4[8][4];

    const int tid = threadIdx.x;
    const int w   = tid >> 5;
    const int l   = tid & 31;

    if (blockIdx.x == 0) {
        if (tid == 0) g_done = 0;
        // build phi LUT: entry i covers t in [i, i+1]/TABN
        for (int e = tid; e < TABN; e += 256) {
            float t0 = (float)e / (float)TABN;
            float t1 = (float)(e + 1) / (float)TABN;
            float f0 = phi_of_t(t0, K1);
            float f1 = phi_of_t(t1, K1);
            g_tab[e] = make_float2(f0, f1 - f0);
        }
    }

    for (int i = tid; i < 2048; i += 256) { sWe1[i] = We1[i]; sWd3[i] = Wd3[i]; }
    for (int i = tid; i < 512;  i += 256) { sWe2[i] = We2[i]; sWd2[i] = Wd2[i]; }
    if (tid < 32) { sWe3[tid] = We3[tid]; sWd1[tid] = Wd1[tid]; sBe1[tid] = be1[tid]; sBd2[tid] = bd2[tid]; }
    if (tid < 16) { sBe2[tid] = be2[tid]; sBd1[tid] = bd1[tid]; }
    if (tid < 2)  { sBe3[tid] = be3[tid]; }
    if (tid < 64) { sBd3[tid] = bd3[tid]; }
    if (tid < 20) sMu[tid] = means[tid];
    if (tid < 10) {
        float v = vars[tid], p = probs[tid];
        sClsC[tid]  = logf(p) - logf(2.f * (float)M_PI * v);
        sInv2v[tid] = 0.5f / v;
        float vp2g = v + 2.f * gam;
        sBcoef[tid] = 2.f * p / ((float)MROWS * sqrtf(2.f * (float)M_PI * vp2g));
        sBinv[tid]  = 0.5f / vp2g;
    }
    __syncthreads();

    float rec_acc = 0.f, ce_acc = 0.f, b_acc = 0.f, den_acc = 0.f;
    {
        int row = blockIdx.x * 8 + w;
        const float* rowp = bd + row * ROWSTRIDE;
        float t0 = rowp[l];
        float t1 = rowp[32 + l];
        float lab = (l < 10) ? rowp[64 + l] : 0.f;
        stau[w][l] = t0; stau[w][32 + l] = t1;
        __syncwarp();

        float a1 = sBe1[l];
        #pragma unroll 16
        for (int k = 0; k < 64; k++) a1 = fmaf(stau[w][k], sWe1[k * 32 + l], a1);
        sh1[w][l] = ftanh(a1);
        __syncwarp();

        int j16 = l & 15;
        float a2 = sBe2[j16];
        #pragma unroll 8
        for (int k = 0; k < 32; k++) a2 = fmaf(sh1[w][k], sWe2[k * 16 + j16], a2);
        if (l < 16) sh2[w][l] = ftanh(a2);
        __syncwarp();

        int j2 = l & 1;
        float a3 = sBe3[j2];
        #pragma unroll
        for (int k = 0; k < 16; k++) a3 = fmaf(sh2[w][k], sWe3[k * 2 + j2], a3);
        float z0 = __shfl_sync(FULLMASK, a3, 0);
        float z1 = __shfl_sync(FULLMASK, a3, 1);
        if (l == 0) g_zs[row] = make_float2(z0 * rsc, z1 * rsc);

        float ad1 = sBd1[j16] + z0 * sWd1[j16] + z1 * sWd1[16 + j16];
        if (l < 16) sd1[w][l] = ftanh(ad1);
        __syncwarp();

        float ad2 = sBd2[l];
        #pragma unroll
        for (int k = 0; k < 16; k++) ad2 = fmaf(sd1[w][k], sWd2[k * 32 + l], ad2);
        sd2[w][l] = ftanh(ad2);
        __syncwarp();

        float o0 = sBd3[l], o1 = sBd3[32 + l];
        #pragma unroll 8
        for (int k = 0; k < 32; k++) {
            float dk = sd2[w][k];
            o0 = fmaf(dk, sWd3[k * 64 + l], o0);
            o1 = fmaf(dk, sWd3[k * 64 + 32 + l], o1);
        }
        float e0 = t0 - o0, e1 = t1 - o1;
        rec_acc += e0 * e0 + e1 * e1;

        int j = (l < 10) ? l : 0;
        float dz0 = z0 - sMu[2 * j], dz1 = z1 - sMu[2 * j + 1];
        float sq = dz0 * dz0 + dz1 * dz1;
        float logit = sClsC[j] - sq * sInv2v[j];
        float lm = (l < 10) ? logit : -1e30f;
        float mx = wmax(lm);
        float ex = (l < 10) ? __expf(logit - mx) : 0.f;
        float Z = wsum(ex);
        float lsm = logit - mx - __logf(Z);
        float labsum = wsum(lab);
        float maskf = (labsum == 1.0f) ? 1.f : 0.f;
        ce_acc += (l < 10) ? (-lab * lsm * maskf) : 0.f;
        if (l == 0) den_acc += labsum;
        b_acc += (l < 10) ? sBcoef[j] * phi_sel(sq * sBinv[j], K1) : 0.f;
    }

    rec_acc = wsum(rec_acc);
    ce_acc  = wsum(ce_acc);
    b_acc   = wsum(b_acc);
    den_acc = wsum(den_acc);
    if (l == 0) {
        sRed4[w][0] = (double)rec_acc; sRed4[w][1] = (double)ce_acc;
        sRed4[w][2] = (double)b_acc;   sRed4[w][3] = (double)den_acc;
    }
    __syncthreads();
    if (tid == 0) {
        double r0 = 0, r1 = 0, r2 = 0, r3 = 0;
        for (int i = 0; i < 8; i++) { r0 += sRed4[i][0]; r1 += sRed4[i][1]; r2 += sRed4[i][2]; r3 += sRed4[i][3]; }
        g_rowp[blockIdx.x][0] = r0; g_rowp[blockIdx.x][1] = r1;
        g_rowp[blockIdx.x][2] = r2; g_rowp[blockIdx.x][3] = r3;
    }
}

// ---------------- pairs kernel: LUT phi, 128x128 tiles, 4i x 16j ----------
__global__ void __launch_bounds__(256) k_pairs(
    const float* __restrict__ means, const float* __restrict__ vars,
    const float* __restrict__ probs, float* __restrict__ out,
    float K1, float gam, double phi0, double scaleA)
{
    __shared__ float2 sTab[TABN];
    __shared__ float2 zi[GRP], zj[GRP];
    __shared__ double sRed[8];
    __shared__ bool sLast;

    const int tid = threadIdx.x;
    const int w   = tid >> 5;
    const int l   = tid & 31;
    const int bid = blockIdx.x;

    int ci = 0, rem = bid;
    for (;;) { int rl = NGRP - ci; if (rem < rl) break; rem -= rl; ci++; }
    const int cj = ci + rem;
    const bool diag = (ci == cj);

    // stage LUT + z tiles
    for (int i = tid; i < TABN; i += 256) sTab[i] = g_tab[i];
    if (tid < GRP) zi[tid] = g_zs[ci * GRP + tid];
    else zj[tid - GRP] = g_zs[cj * GRP + (tid - GRP)];
    __syncthreads();

    const int q  = l;
    const int jw = w;
    float ax0 = zi[q * 4 + 0].x, ay0 = zi[q * 4 + 0].y;
    float ax1 = zi[q * 4 + 1].x, ay1 = zi[q * 4 + 1].y;
    float ax2 = zi[q * 4 + 2].x, ay2 = zi[q * 4 + 2].y;
    float ax3 = zi[q * 4 + 3].x, ay3 = zi[q * 4 + 3].y;

    float acc0 = 0.f, acc1 = 0.f, acc2 = 0.f, acc3 = 0.f;

    #define PHI_LUT(dxv, dyv, dst) do {                                 \
        float u_ = fmaf((dxv), (dxv), fmaf((dyv), (dyv), 1.0f));        \
        float t_ = rsqa(u_);                                            \
        float fi_ = t_ * (float)TABN;                                   \
        int ix_ = __float2int_rd(fi_);                                  \
        ix_ = min(ix_, TABN - 1);                                       \
        float x_ = fi_ - (float)ix_;                                    \
        float2 c_ = sTab[ix_];                                          \
        dst = fmaf(c_.y, x_, c_.x);                                     \
    } while (0)

    if (!diag) {
        #pragma unroll 4
        for (int k = 0; k < 16; k++) {
            float2 b = zj[jw * 16 + k];
            float dx, dy, v;
            dx = ax0 - b.x; dy = ay0 - b.y; PHI_LUT(dx, dy, v); acc0 += v;
            dx = ax1 - b.x; dy = ay1 - b.y; PHI_LUT(dx, dy, v); acc1 += v;
            dx = ax2 - b.x; dy = ay2 - b.y; PHI_LUT(dx, dy, v); acc2 += v;
            dx = ax3 - b.x; dy = ay3 - b.y; PHI_LUT(dx, dy, v); acc3 += v;
        }
    } else {
        const int i0 = q * 4;
        #pragma unroll 4
        for (int k = 0; k < 16; k++) {
            int jl = jw * 16 + k;
            float2 b = zj[jl];
            float dx, dy, v;
            dx = ax0 - b.x; dy = ay0 - b.y; PHI_LUT(dx, dy, v); acc0 += (jl > i0) ? v : 0.f;
            dx = ax1 - b.x; dy = ay1 - b.y; PHI_LUT(dx, dy, v); acc1 += (jl > i0 + 1) ? v : 0.f;
            dx = ax2 - b.x; dy = ay2 - b.y; PHI_LUT(dx, dy, v); acc2 += (jl > i0 + 2) ? v : 0.f;
            dx = ax3 - b.x; dy = ay3 - b.y; PHI_LUT(dx, dy, v); acc3 += (jl > i0 + 3) ? v : 0.f;
        }
    }
    float acc = (acc0 + acc1) + (acc2 + acc3);
    acc = wsum(acc);
    if (l == 0) sRed[w] = (double)acc;
    __syncthreads();
    if (tid == 0) {
        double s = 0;
        for (int i = 0; i < 8; i++) s += sRed[i];
        g_pairp[bid] = s;
        __threadfence();
        unsigned v = atomicAdd(&g_done, 1u);
        sLast = (v == (unsigned)(NTILES - 1));
    }
    __syncthreads();
    if (!sLast) return;
    __threadfence();

    // ---- fused finalize (last block only) ----
    double ps = 0.0;
    for (int i = tid; i < NTILES; i += 256) ps += g_pairp[i];
    double r0 = g_rowp[tid][0] + g_rowp[tid + 256][0];
    double r1 = g_rowp[tid][1] + g_rowp[tid + 256][1];
    double r2 = g_rowp[tid][2] + g_rowp[tid + 256][2];
    double r3 = g_rowp[tid][3] + g_rowp[tid + 256][3];
    double c = 0.0;
    if (tid < 100) {
        int i = tid / 10, j = tid % 10;
        float dx = means[2 * i] - means[2 * j];
        float dy = means[2 * i + 1] - means[2 * j + 1];
        float c1 = dx * dx + dy * dy;
        float vm = vars[i] + vars[j];
        float x = c1 / (2.f * vm + 4.f * gam);
        float c2 = phi_sel(x, K1);
        float c3 = probs[i] * probs[j] * rsqrtf(2.f * (float)M_PI * (vm + 2.f * gam));
        c = (double)(c3 * c2);
    }
    ps = wsumd(ps); r0 = wsumd(r0); r1 = wsumd(r1);
    r2 = wsumd(r2); r3 = wsumd(r3); c = wsumd(c);
    __shared__ double sF[8][6];
    if (l == 0) {
        sF[w][0] = ps; sF[w][1] = r0; sF[w][2] = r1;
        sF[w][3] = r2; sF[w][4] = r3; sF[w][5] = c;
    }
    __syncthreads();
    if (tid == 0) {
        double Ps = 0, Rec = 0, Ce = 0, Bt = 0, Den = 0, Ct = 0;
        for (int i = 0; i < 8; i++) {
            Ps += sF[i][0]; Rec += sF[i][1]; Ce += sF[i][2];
            Bt += sF[i][3]; Den += sF[i][4]; Ct += sF[i][5];
        }
        double m = (double)MROWS;
        double A = (2.0 * Ps + m * phi0) * scaleA;
        double rec = Rec / (m * 64.0);
        if (Den == 0.0) Den = 1.0;
        double cls = Ce / Den;
        double cw = A - Bt + Ct;
        out[0] = (float)(rec + 8.0 + log(cw) + 2.0 * cls);
    }
}

extern "C" void kernel_launch(void* const* d_in, const int* in_sizes, int n_in,
                              void* d_out, int out_size) {
    const float* bd   = (const float*)d_in[0];
    const float* We1  = (const float*)d_in[1];
    const float* be1  = (const float*)d_in[2];
    const float* We2  = (const float*)d_in[3];
    const float* be2  = (const float*)d_in[4];
    const float* We3  = (const float*)d_in[5];
    const float* be3  = (const float*)d_in[6];
    const float* Wd1  = (const float*)d_in[7];
    const float* bd1  = (const float*)d_in[8];
    const float* Wd2  = (const float*)d_in[9];
    const float* bd2  = (const float*)d_in[10];
    const float* Wd3  = (const float*)d_in[11];
    const float* bd3  = (const float*)d_in[12];
    const float* means = (const float*)d_in[13];
    const float* vars  = (const float*)d_in[14];
    const float* probs = (const float*)d_in[15];
    float* out = (float*)d_out;

    const double m = (double)MROWS;
    const double gamma = pow(4.0 / (3.0 * m), 0.2);
    const double pf75 = exp(-3.75) * (1.0 + 3.5156229 + 3.0899424 + 1.2067492 +
                                      0.2659732 + 0.0360768 + 0.0045813);
    const double pg75 = sqrt(2.0 / 7.5) * (0.39894228 + 0.01328592 + 0.00225319 -
                                           0.00157565 + 0.0091628 - 0.02057706 +
                                           0.02635537 - 0.01647633 + 0.00392377);
    const double K1 = pg75 - pf75;
    const double phi0 = 1.0 + K1;
    const double scaleA = 1.0 / (m * m * sqrt(2.0 * M_PI * 2.0 * gamma));
    const float rsc = (float)(1.0 / sqrt(4.0 * gamma));

    k_rows<<<NROWBLK, 256>>>(bd, We1, be1, We2, be2, We3, be3,
                             Wd1, bd1, Wd2, bd2, Wd3, bd3,
                             means, vars, probs, (float)K1, rsc, (float)gamma);
    k_pairs<<<NTILES, 256>>>(means, vars, probs, out,
                             (float)K1, (float)gamma, phi0, scaleA);
}

// round 11
// speedup vs baseline: 1.3763x; 1.3763x over previous
#include <cuda_runtime.h>
#include <math.h>

#ifndef M_PI
#define M_PI 3.14159265358979323846
#endif

#define MROWS 4096
#define ROWSTRIDE 74
#define GRP 128
#define NGRP 32
#define NTILES 528          // 32*33/2
#define NROWBLK 512
#define TABN 1024           // index = round(t*TABN), entries 0..TABN inclusive
#define FULLMASK 0xffffffffu

__device__ float2 g_zs[MROWS];
__device__ float g_tabN[TABN + 1];      // phi LUT (nearest) over t = rsqrt(1+s)
__device__ double g_pairp[NTILES];
__device__ double g_rowp[NROWBLK][4];   // rec, ce, b, den
__device__ unsigned g_done;

// ---- small branch: poly in s^2, coeffs folded with (1/56.25)^k ----
#define P56 56.25
#define BC0 ((float)(3.5156229 / P56))
#define BC1 ((float)(3.0899424 / (P56 * P56)))
#define BC2 ((float)(1.2067492 / (P56 * P56 * P56)))
#define BC3 ((float)(0.2659732 / (P56 * P56 * P56 * P56)))
#define BC4 ((float)(0.0360768 / (P56 * P56 * P56 * P56 * P56)))
#define BC5 ((float)(0.0045813 / (P56 * P56 * P56 * P56 * P56 * P56)))
// ---- large branch: coeffs folded with sqrt(2)*7.5^k, poly in 1/s ----
#define SQ2 1.4142135623730951
#define QD0 ((float)(0.39894228 * SQ2))
#define QD1 ((float)(0.01328592 * SQ2 * 7.5))
#define QD2 ((float)(0.00225319 * SQ2 * 56.25))
#define QD3 ((float)(-0.00157565 * SQ2 * 421.875))
#define QD4 ((float)(0.0091628 * SQ2 * 3164.0625))
#define QD5 ((float)(-0.02057706 * SQ2 * 23730.46875))
#define QD6 ((float)(0.02635537 * SQ2 * 177978.515625))
#define QD7 ((float)(-0.01647633 * SQ2 * 1334838.8671875))
#define QD8 ((float)(0.00392377 * SQ2 * 10011291.50390625))

__device__ __forceinline__ float rsqa(float x) {
    float r; asm("rsqrt.approx.f32 %0,%1;" : "=f"(r) : "f"(x)); return r;
}

// exact reference phi (rows / finalize / table build)
__device__ __forceinline__ float phi_sel(float s, float K1) {
    float s2 = s * s;
    float p = fmaf(s2, BC5, BC4);
    p = fmaf(s2, p, BC3);
    p = fmaf(s2, p, BC2);
    p = fmaf(s2, p, BC1);
    p = fmaf(s2, p, BC0);
    p = fmaf(s2, p, 1.0f);
    float e  = __expf(-0.5f * s);
    float sv = fmaf(p, e, K1);
    float r  = rsqrtf(s);
    float iv = r * r;
    float q = fmaf(iv, QD8, QD7);
    q = fmaf(iv, q, QD6);
    q = fmaf(iv, q, QD5);
    q = fmaf(iv, q, QD4);
    q = fmaf(iv, q, QD3);
    q = fmaf(iv, q, QD2);
    q = fmaf(iv, q, QD1);
    q = fmaf(iv, q, QD0);
    float bv = r * q;
    return (s <= 7.5f) ? sv : bv;
}

__device__ __forceinline__ float phi_of_t(float t, float K1) {
    if (t <= 0.f) return 0.f;
    double td = (double)t;
    double sd = 1.0 / (td * td) - 1.0;
    if (sd < 0.0) sd = 0.0;
    return phi_sel((float)sd, K1);
}

__device__ __forceinline__ float ftanh(float x) {
    float e = __expf(2.f * x);
    return 1.f - __fdividef(2.f, e + 1.f);
}
__device__ __forceinline__ float wsum(float v) {
    #pragma unroll
    for (int o = 16; o; o >>= 1) v += __shfl_xor_sync(FULLMASK, v, o);
    return v;
}
__device__ __forceinline__ double wsumd(double v) {
    #pragma unroll
    for (int o = 16; o; o >>= 1) v += __shfl_xor_sync(FULLMASK, v, o);
    return v;
}
__device__ __forceinline__ float wmax(float v) {
    #pragma unroll
    for (int o = 16; o; o >>= 1) v = fmaxf(v, __shfl_xor_sync(FULLMASK, v, o));
    return v;
}

// ---------------- rows kernel: 512 blocks, 1 row/warp; block 0 builds LUT ----
__global__ void __launch_bounds__(256) k_rows(
    const float* __restrict__ bd,
    const float* __restrict__ We1, const float* __restrict__ be1,
    const float* __restrict__ We2, const float* __restrict__ be2,
    const float* __restrict__ We3, const float* __restrict__ be3,
    const float* __restrict__ Wd1, const float* __restrict__ bd1,
    const float* __restrict__ Wd2, const float* __restrict__ bd2,
    const float* __restrict__ Wd3, const float* __restrict__ bd3,
    const float* __restrict__ means, const float* __restrict__ vars,
    const float* __restrict__ probs,
    float K1, float rsc, float gam)
{
    __shared__ float sWe1[2048], sWe2[512], sWe3[32], sWd1[32], sWd2[512], sWd3[2048];
    __shared__ float sBe1[32], sBe2[16], sBe3[2], sBd1[16], sBd2[32], sBd3[64];
    __shared__ float sClsC[10], sInv2v[10], sBcoef[10], sBinv[10], sMu[20];
    __shared__ float stau[8][64], sh1[8][32], sh2[8][16], sd1[8][16], sd2[8][32];
    __shared__ double sRed4[8][4];

    const int tid = threadIdx.x;
    const int w   = tid >> 5;
    const int l   = tid & 31;

    if (blockIdx.x == 0) {
        if (tid == 0) g_done = 0;
        // build nearest-phi LUT: entry i represents t = i/TABN
        for (int e = tid; e <= TABN; e += 256) {
            float t = (float)e / (float)TABN;
            g_tabN[e] = phi_of_t(t, K1);
        }
    }

    for (int i = tid; i < 2048; i += 256) { sWe1[i] = We1[i]; sWd3[i] = Wd3[i]; }
    for (int i = tid; i < 512;  i += 256) { sWe2[i] = We2[i]; sWd2[i] = Wd2[i]; }
    if (tid < 32) { sWe3[tid] = We3[tid]; sWd1[tid] = Wd1[tid]; sBe1[tid] = be1[tid]; sBd2[tid] = bd2[tid]; }
    if (tid < 16) { sBe2[tid] = be2[tid]; sBd1[tid] = bd1[tid]; }
    if (tid < 2)  { sBe3[tid] = be3[tid]; }
    if (tid < 64) { sBd3[tid] = bd3[tid]; }
    if (tid < 20) sMu[tid] = means[tid];
    if (tid < 10) {
        float v = vars[tid], p = probs[tid];
        sClsC[tid]  = logf(p) - logf(2.f * (float)M_PI * v);
        sInv2v[tid] = 0.5f / v;
        float vp2g = v + 2.f * gam;
        sBcoef[tid] = 2.f * p / ((float)MROWS * sqrtf(2.f * (float)M_PI * vp2g));
        sBinv[tid]  = 0.5f / vp2g;
    }
    __syncthreads();

    float rec_acc = 0.f, ce_acc = 0.f, b_acc = 0.f, den_acc = 0.f;
    {
        int row = blockIdx.x * 8 + w;
        const float* rowp = bd + row * ROWSTRIDE;
        float t0 = rowp[l];
        float t1 = rowp[32 + l];
        float lab = (l < 10) ? rowp[64 + l] : 0.f;
        stau[w][l] = t0; stau[w][32 + l] = t1;
        __syncwarp();

        float a1 = sBe1[l];
        #pragma unroll 16
        for (int k = 0; k < 64; k++) a1 = fmaf(stau[w][k], sWe1[k * 32 + l], a1);
        sh1[w][l] = ftanh(a1);
        __syncwarp();

        int j16 = l & 15;
        float a2 = sBe2[j16];
        #pragma unroll 8
        for (int k = 0; k < 32; k++) a2 = fmaf(sh1[w][k], sWe2[k * 16 + j16], a2);
        if (l < 16) sh2[w][l] = ftanh(a2);
        __syncwarp();

        int j2 = l & 1;
        float a3 = sBe3[j2];
        #pragma unroll
        for (int k = 0; k < 16; k++) a3 = fmaf(sh2[w][k], sWe3[k * 2 + j2], a3);
        float z0 = __shfl_sync(FULLMASK, a3, 0);
        float z1 = __shfl_sync(FULLMASK, a3, 1);
        if (l == 0) g_zs[row] = make_float2(z0 * rsc, z1 * rsc);

        float ad1 = sBd1[j16] + z0 * sWd1[j16] + z1 * sWd1[16 + j16];
        if (l < 16) sd1[w][l] = ftanh(ad1);
        __syncwarp();

        float ad2 = sBd2[l];
        #pragma unroll
        for (int k = 0; k < 16; k++) ad2 = fmaf(sd1[w][k], sWd2[k * 32 + l], ad2);
        sd2[w][l] = ftanh(ad2);
        __syncwarp();

        float o0 = sBd3[l], o1 = sBd3[32 + l];
        #pragma unroll 8
        for (int k = 0; k < 32; k++) {
            float dk = sd2[w][k];
            o0 = fmaf(dk, sWd3[k * 64 + l], o0);
            o1 = fmaf(dk, sWd3[k * 64 + 32 + l], o1);
        }
        float e0 = t0 - o0, e1 = t1 - o1;
        rec_acc += e0 * e0 + e1 * e1;

        int j = (l < 10) ? l : 0;
        float dz0 = z0 - sMu[2 * j], dz1 = z1 - sMu[2 * j + 1];
        float sq = dz0 * dz0 + dz1 * dz1;
        float logit = sClsC[j] - sq * sInv2v[j];
        float lm = (l < 10) ? logit : -1e30f;
        float mx = wmax(lm);
        float ex = (l < 10) ? __expf(logit - mx) : 0.f;
        float Z = wsum(ex);
        float lsm = logit - mx - __logf(Z);
        float labsum = wsum(lab);
        float maskf = (labsum == 1.0f) ? 1.f : 0.f;
        ce_acc += (l < 10) ? (-lab * lsm * maskf) : 0.f;
        if (l == 0) den_acc += labsum;
        b_acc += (l < 10) ? sBcoef[j] * phi_sel(sq * sBinv[j], K1) : 0.f;
    }

    rec_acc = wsum(rec_acc);
    ce_acc  = wsum(ce_acc);
    b_acc   = wsum(b_acc);
    den_acc = wsum(den_acc);
    if (l == 0) {
        sRed4[w][0] = (double)rec_acc; sRed4[w][1] = (double)ce_acc;
        sRed4[w][2] = (double)b_acc;   sRed4[w][3] = (double)den_acc;
    }
    __syncthreads();
    if (tid == 0) {
        double r0 = 0, r1 = 0, r2 = 0, r3 = 0;
        for (int i = 0; i < 8; i++) { r0 += sRed4[i][0]; r1 += sRed4[i][1]; r2 += sRed4[i][2]; r3 += sRed4[i][3]; }
        g_rowp[blockIdx.x][0] = r0; g_rowp[blockIdx.x][1] = r1;
        g_rowp[blockIdx.x][2] = r2; g_rowp[blockIdx.x][3] = r3;
    }
}

// ---------------- pairs kernel: nearest-LUT phi, 128x128 tiles, 4i x 16j ----
__global__ void __launch_bounds__(256) k_pairs(
    const float* __restrict__ means, const float* __restrict__ vars,
    const float* __restrict__ probs, float* __restrict__ out,
    float K1, float gam, double phi0, double scaleA)
{
    __shared__ float sTab[TABN + 1];
    __shared__ float2 zi[GRP], zj[GRP];
    __shared__ double sRed[8];
    __shared__ bool sLast;

    const int tid = threadIdx.x;
    const int w   = tid >> 5;
    const int l   = tid & 31;
    const int bid = blockIdx.x;

    int ci = 0, rem = bid;
    for (;;) { int rl = NGRP - ci; if (rem < rl) break; rem -= rl; ci++; }
    const int cj = ci + rem;
    const bool diag = (ci == cj);

    // stage LUT + z tiles
    for (int i = tid; i <= TABN; i += 256) sTab[i] = g_tabN[i];
    if (tid < GRP) zi[tid] = g_zs[ci * GRP + tid];
    else zj[tid - GRP] = g_zs[cj * GRP + (tid - GRP)];
    __syncthreads();

    const int q  = l;
    const int jw = w;
    float ax0 = zi[q * 4 + 0].x, ay0 = zi[q * 4 + 0].y;
    float ax1 = zi[q * 4 + 1].x, ay1 = zi[q * 4 + 1].y;
    float ax2 = zi[q * 4 + 2].x, ay2 = zi[q * 4 + 2].y;
    float ax3 = zi[q * 4 + 3].x, ay3 = zi[q * 4 + 3].y;

    float acc0 = 0.f, acc1 = 0.f, acc2 = 0.f, acc3 = 0.f;

    #define PHI_NEAR(dxv, dyv, dst) do {                                \
        float u_ = fmaf((dxv), (dxv), fmaf((dyv), (dyv), 1.0f));        \
        float t_ = rsqa(u_);                                            \
        int ix_ = __float2int_rn(t_ * (float)TABN);                     \
        ix_ = min(ix_, TABN);                                           \
        dst = sTab[ix_];                                                \
    } while (0)

    if (!diag) {
        #pragma unroll 4
        for (int k = 0; k < 16; k++) {
            float2 b = zj[jw * 16 + k];
            float dx, dy, v;
            dx = ax0 - b.x; dy = ay0 - b.y; PHI_NEAR(dx, dy, v); acc0 += v;
            dx = ax1 - b.x; dy = ay1 - b.y; PHI_NEAR(dx, dy, v); acc1 += v;
            dx = ax2 - b.x; dy = ay2 - b.y; PHI_NEAR(dx, dy, v); acc2 += v;
            dx = ax3 - b.x; dy = ay3 - b.y; PHI_NEAR(dx, dy, v); acc3 += v;
        }
    } else {
        const int i0 = q * 4;
        #pragma unroll 4
        for (int k = 0; k < 16; k++) {
            int jl = jw * 16 + k;
            float2 b = zj[jl];
            float dx, dy, v;
            dx = ax0 - b.x; dy = ay0 - b.y; PHI_NEAR(dx, dy, v); acc0 += (jl > i0) ? v : 0.f;
            dx = ax1 - b.x; dy = ay1 - b.y; PHI_NEAR(dx, dy, v); acc1 += (jl > i0 + 1) ? v : 0.f;
            dx = ax2 - b.x; dy = ay2 - b.y; PHI_NEAR(dx, dy, v); acc2 += (jl > i0 + 2) ? v : 0.f;
            dx = ax3 - b.x; dy = ay3 - b.y; PHI_NEAR(dx, dy, v); acc3 += (jl > i0 + 3) ? v : 0.f;
        }
    }
    float acc = (acc0 + acc1) + (acc2 + acc3);
    acc = wsum(acc);
    if (l == 0) sRed[w] = (double)acc;
    __syncthreads();
    if (tid == 0) {
        double s = 0;
        for (int i = 0; i < 8; i++) s += sRed[i];
        g_pairp[bid] = s;
        __threadfence();
        unsigned v = atomicAdd(&g_done, 1u);
        sLast = (v == (unsigned)(NTILES - 1));
    }
    __syncthreads();
    if (!sLast) return;
    __threadfence();

    // ---- fused finalize (last block only) ----
    double ps = 0.0;
    for (int i = tid; i < NTILES; i += 256) ps += g_pairp[i];
    double r0 = g_rowp[tid][0] + g_rowp[tid + 256][0];
    double r1 = g_rowp[tid][1] + g_rowp[tid + 256][1];
    double r2 = g_rowp[tid][2] + g_rowp[tid + 256][2];
    double r3 = g_rowp[tid][3] + g_rowp[tid + 256][3];
    double c = 0.0;
    if (tid < 100) {
        int i = tid / 10, j = tid % 10;
        float dx = means[2 * i] - means[2 * j];
        float dy = means[2 * i + 1] - means[2 * j + 1];
        float c1 = dx * dx + dy * dy;
        float vm = vars[i] + vars[j];
        float x = c1 / (2.f * vm + 4.f * gam);
        float c2 = phi_sel(x, K1);
        float c3 = probs[i] * probs[j] * rsqrtf(2.f * (float)M_PI * (vm + 2.f * gam));
        c = (double)(c3 * c2);
    }
    ps = wsumd(ps); r0 = wsumd(r0); r1 = wsumd(r1);
    r2 = wsumd(r2); r3 = wsumd(r3); c = wsumd(c);
    __shared__ double sF[8][6];
    if (l == 0) {
        sF[w][0] = ps; sF[w][1] = r0; sF[w][2] = r1;
        sF[w][3] = r2; sF[w][4] = r3; sF[w][5] = c;
    }
    __syncthreads();
    if (tid == 0) {
        double Ps = 0, Rec = 0, Ce = 0, Bt = 0, Den = 0, Ct = 0;
        for (int i = 0; i < 8; i++) {
            Ps += sF[i][0]; Rec += sF[i][1]; Ce += sF[i][2];
            Bt += sF[i][3]; Den += sF[i][4]; Ct += sF[i][5];
        }
        double m = (double)MROWS;
        double A = (2.0 * Ps + m * phi0) * scaleA;
        double rec = Rec / (m * 64.0);
        if (Den == 0.0) Den = 1.0;
        double cls = Ce / Den;
        double cw = A - Bt + Ct;
        out[0] = (float)(rec + 8.0 + log(cw) + 2.0 * cls);
    }
}

extern "C" void kernel_launch(void* const* d_in, const int* in_sizes, int n_in,
                              void* d_out, int out_size) {
    const float* bd   = (const float*)d_in[0];
    const float* We1  = (const float*)d_in[1];
    const float* be1  = (const float*)d_in[2];
    const float* We2  = (const float*)d_in[3];
    const float* be2  = (const float*)d_in[4];
    const float* We3  = (const float*)d_in[5];
    const float* be3  = (const float*)d_in[6];
    const float* Wd1  = (const float*)d_in[7];
    const float* bd1  = (const float*)d_in[8];
    const float* Wd2  = (const float*)d_in[9];
    const float* bd2  = (const float*)d_in[10];
    const float* Wd3  = (const float*)d_in[11];
    const float* bd3  = (const float*)d_in[12];
    const float* means = (const float*)d_in[13];
    const float* vars  = (const float*)d_in[14];
    const float* probs = (const float*)d_in[15];
    float* out = (float*)d_out;

    const double m = (double)MROWS;
    const double gamma = pow(4.0 / (3.0 * m), 0.2);
    const double pf75 = exp(-3.75) * (1.0 + 3.5156229 + 3.0899424 + 1.2067492 +
                                      0.2659732 + 0.0360768 + 0.0045813);
    const double pg75 = sqrt(2.0 / 7.5) * (0.39894228 + 0.01328592 + 0.00225319 -
                                           0.00157565 + 0.0091628 - 0.02057706 +
                                           0.02635537 - 0.01647633 + 0.00392377);
    const double K1 = pg75 - pf75;
    const double phi0 = 1.0 + K1;
    const double scaleA = 1.0 / (m * m * sqrt(2.0 * M_PI * 2.0 * gamma));
    const float rsc = (float)(1.0 / sqrt(4.0 * gamma));

    k_rows<<<NROWBLK, 256>>>(bd, We1, be1, We2, be2, We3, be3,
                             Wd1, bd1, Wd2, bd2, Wd3, bd3,
                             means, vars, probs, (float)K1, rsc, (float)gamma);
    k_pairs<<<NTILES, 256>>>(means, vars, probs, out,
                             (float)K1, (float)gamma, phi0, scaleA);
}